// round 3
// baseline (speedup 1.0000x reference)
#include <cuda_runtime.h>
#include <cstdint>
#include <math.h>

// Problem constants (fixed shapes from reference)
#define B_N   16384
#define K_N   50
#define D_N   64
#define R_N   8
#define V_N   100000
#define BK_N  (B_N * K_N)          // 819200

typedef unsigned long long u64;

// ---------------------------------------------------------------------------
// Packed f32x2 helpers (Blackwell sm_100+). ptxas never auto-fuses these.
// ---------------------------------------------------------------------------
__device__ __forceinline__ u64 ffma2(u64 a, u64 b, u64 c) {
    u64 d;
    asm("fma.rn.f32x2 %0, %1, %2, %3;" : "=l"(d) : "l"(a), "l"(b), "l"(c));
    return d;
}
__device__ __forceinline__ u64 fadd2(u64 a, u64 b) {
    u64 d;
    asm("add.rn.f32x2 %0, %1, %2;" : "=l"(d) : "l"(a), "l"(b));
    return d;
}
__device__ __forceinline__ u64 pack2s(float x) {          // {x, x}
    u64 d;
    asm("mov.b64 %0, {%1, %1};" : "=l"(d) : "f"(x));
    return d;
}
__device__ __forceinline__ float2 unpack2(u64 v) {
    float2 f;
    asm("mov.b64 {%0, %1}, %2;" : "=f"(f.x), "=f"(f.y) : "l"(v));
    return f;
}

// ---------------------------------------------------------------------------
// Device scratch (static — no cudaMalloc allowed)
// ---------------------------------------------------------------------------
__device__ float g_P  [(size_t)V_N * D_N];     // u2e @ w1_W[0:64,:]   25.6 MB
__device__ float g_A1B[(size_t)V_N * D_N];     // u2e @ a1_W[64:128,:] 25.6 MB
__device__ float g_O  [(size_t)BK_N * D_N];    // o_history            209.7 MB
__device__ float g_S  [(size_t)BK_N];          // attention scores     3.3 MB

// ---------------------------------------------------------------------------
// Kernel 0: per-vocab precompute. Thread-per-row, register accumulators,
// packed FFMA2, weights in shared. No per-iteration barriers.
// A 64-float output row = 32 u64 accumulators = 16 ulonglong2 chunks.
// ---------------------------------------------------------------------------
__global__ void __launch_bounds__(128) k_pre(const float* __restrict__ u2e,
                                             const float* __restrict__ w1W,
                                             const float* __restrict__ a1W)
{
    __shared__ float sW1[64 * 64];
    __shared__ float sA1[64 * 64];

    const int tid = threadIdx.x;
    for (int t = tid; t < 4096; t += 128) {
        sW1[t] = w1W[t];            // rows 0..63 of w1_W
        sA1[t] = a1W[4096 + t];     // rows 64..127 of a1_W
    }
    __syncthreads();

    const int v = blockIdx.x * 128 + tid;
    if (v >= V_N) return;

    float x[64];
    {
        const float4* uv = reinterpret_cast<const float4*>(u2e + (size_t)v * 64);
        #pragma unroll
        for (int q = 0; q < 16; q++) {
            const float4 t = uv[q];
            x[4*q+0] = t.x; x[4*q+1] = t.y; x[4*q+2] = t.z; x[4*q+3] = t.w;
        }
    }

    u64 acc[32];

    // ---- P = u @ W1[0:64] ----
    #pragma unroll
    for (int q = 0; q < 32; q++) acc[q] = 0ull;
    {
        const ulonglong2* Wv = reinterpret_cast<const ulonglong2*>(sW1);
        #pragma unroll 4
        for (int i = 0; i < 64; i++) {
            const u64 xx = pack2s(x[i]);
            #pragma unroll
            for (int q = 0; q < 16; q++) {
                const ulonglong2 w = Wv[i * 16 + q];
                acc[2*q]   = ffma2(xx, w.x, acc[2*q]);
                acc[2*q+1] = ffma2(xx, w.y, acc[2*q+1]);
            }
        }
        ulonglong2* Pv = reinterpret_cast<ulonglong2*>(g_P + (size_t)v * 64);
        #pragma unroll
        for (int q = 0; q < 16; q++) Pv[q] = make_ulonglong2(acc[2*q], acc[2*q+1]);
    }

    // ---- A1B = u @ a1_W[64:128] ----
    #pragma unroll
    for (int q = 0; q < 32; q++) acc[q] = 0ull;
    {
        const ulonglong2* Wv = reinterpret_cast<const ulonglong2*>(sA1);
        #pragma unroll 4
        for (int i = 0; i < 64; i++) {
            const u64 xx = pack2s(x[i]);
            #pragma unroll
            for (int q = 0; q < 16; q++) {
                const ulonglong2 w = Wv[i * 16 + q];
                acc[2*q]   = ffma2(xx, w.x, acc[2*q]);
                acc[2*q+1] = ffma2(xx, w.y, acc[2*q+1]);
            }
        }
        ulonglong2* Av = reinterpret_cast<ulonglong2*>(g_A1B + (size_t)v * 64);
        #pragma unroll
        for (int q = 0; q < 16; q++) Av[q] = make_ulonglong2(acc[2*q], acc[2*q+1]);
    }
}

// ---------------------------------------------------------------------------
// Kernel 1: per-(b,k)-pair fused MLP chain, packed FFMA2 throughout.
// ---------------------------------------------------------------------------
#define SMEM_FLOATS 13120   // 3*4096 + 512 + 5*64
#define SMEM_BYTES  (SMEM_FLOATS * 4)

__global__ void __launch_bounds__(128, 2) k_pairs(
    const int*   __restrict__ nodes,
    const int*   __restrict__ nidx,
    const float* __restrict__ labels,
    const float* __restrict__ w1W,
    const float* __restrict__ w1b,
    const float* __restrict__ w2W,
    const float* __restrict__ w2b,
    const float* __restrict__ a1W,
    const float* __restrict__ a1b,
    const float* __restrict__ a2W,
    const float* __restrict__ a2b,
    const float* __restrict__ a3W,
    const float* __restrict__ a3b)
{
    extern __shared__ float smem[];
    float* sW2  = smem;             // 4096
    float* sA1  = smem + 4096;      // 4096  (rows 0..63 of a1_W)
    float* sA2  = smem + 8192;      // 4096
    float* sW1L = smem + 12288;     // 512   (rows 64..71 of w1_W — labels part)
    float* sB1  = smem + 12800;     // 64
    float* sB2  = smem + 12864;     // 64
    float* sBa1 = smem + 12928;     // 64
    float* sBa2 = smem + 12992;     // 64
    float* sA3  = smem + 13056;     // 64

    const int tid = threadIdx.x;
    for (int t = tid; t < 4096; t += 128) {
        sW2[t] = w2W[t];
        sA1[t] = a1W[t];
        sA2[t] = a2W[t];
    }
    for (int t = tid; t < 512; t += 128) sW1L[t] = w1W[4096 + t];
    if (tid < 64) {
        sB1 [tid] = w1b[tid];
        sB2 [tid] = w2b[tid];
        sBa1[tid] = a1b[tid];
        sBa2[tid] = a2b[tid];
        sA3 [tid] = a3W[tid];
    }
    __syncthreads();

    const float a3b0 = a3b[0];

    for (int p = blockIdx.x * 128 + tid; p < BK_N; p += gridDim.x * 128) {
        const int b    = p / K_N;
        const int node = nodes[b];
        const int ni   = nidx[p];

        u64   acc[32];
        float x[64];

        // ---- Layer 1: h = relu(P[ni] + labels @ W1L + b1) ----
        {
            const ulonglong2* Pv = reinterpret_cast<const ulonglong2*>(g_P + (size_t)ni * 64);
            const ulonglong2* Bv = reinterpret_cast<const ulonglong2*>(sB1);
            #pragma unroll
            for (int q = 0; q < 16; q++) {
                const ulonglong2 pw = Pv[q];
                const ulonglong2 bw = Bv[q];
                acc[2*q]   = fadd2(pw.x, bw.x);
                acc[2*q+1] = fadd2(pw.y, bw.y);
            }

            const float4* lv = reinterpret_cast<const float4*>(labels + (size_t)p * 8);
            const float4 la = lv[0], lb = lv[1];
            const float lab[8] = { la.x, la.y, la.z, la.w, lb.x, lb.y, lb.z, lb.w };

            const ulonglong2* Wv = reinterpret_cast<const ulonglong2*>(sW1L);
            #pragma unroll
            for (int r = 0; r < 8; r++) {
                const u64 lr = pack2s(lab[r]);
                #pragma unroll
                for (int q = 0; q < 16; q++) {
                    const ulonglong2 w = Wv[r * 16 + q];
                    acc[2*q]   = ffma2(lr, w.x, acc[2*q]);
                    acc[2*q+1] = ffma2(lr, w.y, acc[2*q+1]);
                }
            }
            #pragma unroll
            for (int q = 0; q < 32; q++) {
                const float2 f = unpack2(acc[q]);
                x[2*q]   = fmaxf(f.x, 0.f);
                x[2*q+1] = fmaxf(f.y, 0.f);
            }
        }

        // ---- Layers 2..4: x <- relu(x @ W + bias(+A1B gather on L==1)) ----
        #pragma unroll 1
        for (int L = 0; L < 3; L++) {
            const ulonglong2* Wv;
            const ulonglong2* bv;
            if (L == 0)      { Wv = (const ulonglong2*)sW2; bv = (const ulonglong2*)sB2;  }
            else if (L == 1) { Wv = (const ulonglong2*)sA1; bv = (const ulonglong2*)sBa1; }
            else             { Wv = (const ulonglong2*)sA2; bv = (const ulonglong2*)sBa2; }

            if (L == 1) {
                const ulonglong2* Gv = reinterpret_cast<const ulonglong2*>(g_A1B + (size_t)node * 64);
                #pragma unroll
                for (int q = 0; q < 16; q++) {
                    const ulonglong2 bw = bv[q];
                    const ulonglong2 gw = Gv[q];
                    acc[2*q]   = fadd2(bw.x, gw.x);
                    acc[2*q+1] = fadd2(bw.y, gw.y);
                }
            } else {
                #pragma unroll
                for (int q = 0; q < 16; q++) {
                    const ulonglong2 bw = bv[q];
                    acc[2*q]   = bw.x;
                    acc[2*q+1] = bw.y;
                }
            }

            #pragma unroll 4
            for (int i = 0; i < 64; i++) {
                const u64 xx = pack2s(x[i]);
                #pragma unroll
                for (int q = 0; q < 16; q++) {
                    const ulonglong2 w = Wv[i * 16 + q];
                    acc[2*q]   = ffma2(xx, w.x, acc[2*q]);
                    acc[2*q+1] = ffma2(xx, w.y, acc[2*q+1]);
                }
            }

            #pragma unroll
            for (int q = 0; q < 32; q++) {
                const float2 f = unpack2(acc[q]);
                x[2*q]   = fmaxf(f.x, 0.f);
                x[2*q+1] = fmaxf(f.y, 0.f);
            }

            if (L == 0) {   // persist o_history for attention aggregate
                float4* Ov = reinterpret_cast<float4*>(g_O + (size_t)p * 64);
                #pragma unroll
                for (int q = 0; q < 16; q++)
                    Ov[q] = make_float4(x[4*q], x[4*q+1], x[4*q+2], x[4*q+3]);
            }
        }

        // ---- score = x @ a3_W + a3_b ----
        float sc = a3b0;
        #pragma unroll
        for (int j = 0; j < 64; j++) sc = fmaf(x[j], sA3[j], sc);
        g_S[p] = sc;
    }
}

// ---------------------------------------------------------------------------
// Kernel 2: masked softmax over K neighbors + weighted aggregate.
// One warp per node. len==0 -> copy self embedding.
// ---------------------------------------------------------------------------
__global__ void __launch_bounds__(256) k_agg(const int*   __restrict__ nodes,
                                             const int*   __restrict__ nlen,
                                             const float* __restrict__ u2e,
                                             float*       __restrict__ out)
{
    const int wid  = (blockIdx.x * 256 + threadIdx.x) >> 5;
    const int lane = threadIdx.x & 31;
    if (wid >= B_N) return;
    const int b   = wid;
    const int len = nlen[b];

    if (len <= 0) {
        const int node = nodes[b];
        const float2* src = reinterpret_cast<const float2*>(u2e + (size_t)node * 64);
        float2*       dst = reinterpret_cast<float2*>(out + (size_t)b * 64);
        dst[lane] = src[lane];
        return;
    }

    const float* Sb = g_S + (size_t)b * K_N;
    float s0 = (lane      < len) ? Sb[lane]      : -3.0e38f;
    float s1 = (lane + 32 < len) ? Sb[lane + 32] : -3.0e38f;

    float m = fmaxf(s0, s1);
    #pragma unroll
    for (int o = 16; o > 0; o >>= 1) m = fmaxf(m, __shfl_xor_sync(0xffffffffu, m, o));

    const float e0 = (lane      < len) ? expf(s0 - m) : 0.f;
    const float e1 = (lane + 32 < len) ? expf(s1 - m) : 0.f;

    float ss = e0 + e1;
    #pragma unroll
    for (int o = 16; o > 0; o >>= 1) ss += __shfl_xor_sync(0xffffffffu, ss, o);

    const float inv = 1.f / ss;
    const float w0 = e0 * inv;
    const float w1 = e1 * inv;

    float2 agg = make_float2(0.f, 0.f);
    const float2* Ob = reinterpret_cast<const float2*>(g_O + (size_t)b * K_N * 64);
    for (int k = 0; k < len; k++) {
        const float ak = (k < 32) ? __shfl_sync(0xffffffffu, w0, k)
                                  : __shfl_sync(0xffffffffu, w1, k - 32);
        const float2 ov = Ob[k * 32 + lane];
        agg.x = fmaf(ak, ov.x, agg.x);
        agg.y = fmaf(ak, ov.y, agg.y);
    }
    reinterpret_cast<float2*>(out + (size_t)b * 64)[lane] = agg;
}

// ---------------------------------------------------------------------------
// kernel_launch
// ---------------------------------------------------------------------------
extern "C" void kernel_launch(void* const* d_in, const int* in_sizes, int n_in,
                              void* d_out, int out_size)
{
    const int*   nodes  = (const int*)  d_in[0];
    const int*   nidx   = (const int*)  d_in[1];
    const int*   nlen   = (const int*)  d_in[2];
    const float* labels = (const float*)d_in[3];
    const float* u2e    = (const float*)d_in[4];
    const float* w1W    = (const float*)d_in[5];
    const float* w1b    = (const float*)d_in[6];
    const float* w2W    = (const float*)d_in[7];
    const float* w2b    = (const float*)d_in[8];
    const float* a1W    = (const float*)d_in[9];
    const float* a1b    = (const float*)d_in[10];
    const float* a2W    = (const float*)d_in[11];
    const float* a2b    = (const float*)d_in[12];
    const float* a3W    = (const float*)d_in[13];
    const float* a3b    = (const float*)d_in[14];
    float* out = (float*)d_out;

    cudaFuncSetAttribute(k_pairs, cudaFuncAttributeMaxDynamicSharedMemorySize, SMEM_BYTES);

    k_pre  <<<(V_N + 127) / 128, 128>>>(u2e, w1W, a1W);
    k_pairs<<<296, 128, SMEM_BYTES>>>(nodes, nidx, labels,
                                      w1W, w1b, w2W, w2b,
                                      a1W, a1b, a2W, a2b, a3W, a3b);
    k_agg  <<<(B_N * 32 + 255) / 256, 256>>>(nodes, nlen, u2e, out);
}

// round 5
// speedup vs baseline: 3.5555x; 3.5555x over previous
#include <cuda_runtime.h>
#include <cuda_bf16.h>
#include <cstdint>
#include <math.h>

// Problem constants
#define B_N   16384
#define K_N   50
#define V_N   100000
#define BK_N  (B_N * K_N)          // 819200
#define NTILE (BK_N / 128)         // 6400 tiles of 128 pairs

typedef unsigned int u32;

// ---------------------------------------------------------------------------
// Device scratch (static — no cudaMalloc allowed)
// ---------------------------------------------------------------------------
__device__ float g_P  [(size_t)V_N * 64];      // u2e @ w1_W[0:64,:]
__device__ float g_A1B[(size_t)V_N * 64];      // u2e @ a1_W[64:128,:]
__device__ float g_O  [(size_t)BK_N * 64];     // o_history (fp32)
__device__ float g_S  [(size_t)BK_N];          // attention scores
// Weight fragments: [L:3][part:2][kt:4][nt:8][lane:32][reg:2] u32 (bf16x2)
__device__ u32   g_Wf [3 * 2 * 4 * 8 * 32 * 2];   // 12288 u32 = 48KB

// ---------------------------------------------------------------------------
// bf16 helpers
// ---------------------------------------------------------------------------
__device__ __forceinline__ u32 pack_bf16x2(float lo, float hi) {
    u32 d;
    asm("cvt.rn.bf16x2.f32 %0, %1, %2;" : "=r"(d) : "f"(hi), "f"(lo));
    return d;
}
// Split two f32 into packed bf16x2 hi part + bf16x2 residual (lo) part.
__device__ __forceinline__ void split2(float v0, float v1, u32& h, u32& l) {
    h = pack_bf16x2(v0, v1);
    const float r0 = v0 - __uint_as_float(h << 16);
    const float r1 = v1 - __uint_as_float(h & 0xFFFF0000u);
    l = pack_bf16x2(r0, r1);
}
// m16n8k16 row.col bf16 MMA, fp32 accumulate (sm_80+ baseline — no 'a' target)
__device__ __forceinline__ void mma16816(float& d0, float& d1, float& d2, float& d3,
                                         u32 a0, u32 a1, u32 a2, u32 a3,
                                         u32 b0, u32 b1) {
    asm("mma.sync.aligned.m16n8k16.row.col.f32.bf16.bf16.f32 "
        "{%0,%1,%2,%3}, {%4,%5,%6,%7}, {%8,%9}, {%0,%1,%2,%3};"
        : "+f"(d0), "+f"(d1), "+f"(d2), "+f"(d3)
        : "r"(a0), "r"(a1), "r"(a2), "r"(a3), "r"(b0), "r"(b1));
}

// ---------------------------------------------------------------------------
// Kernel 0: per-vocab precompute of P and A1B (scalar fp32; verified)
// ---------------------------------------------------------------------------
__global__ void __launch_bounds__(128) k_pre(const float* __restrict__ u2e,
                                             const float* __restrict__ w1W,
                                             const float* __restrict__ a1W)
{
    __shared__ float sW1[4096];
    __shared__ float sA1[4096];
    const int tid = threadIdx.x;
    for (int t = tid; t < 4096; t += 128) {
        sW1[t] = w1W[t];
        sA1[t] = a1W[4096 + t];
    }
    __syncthreads();

    const int v = blockIdx.x * 128 + tid;
    if (v >= V_N) return;

    float x[64];
    const float4* uv = reinterpret_cast<const float4*>(u2e + (size_t)v * 64);
    #pragma unroll
    for (int q = 0; q < 16; q++) {
        const float4 t = uv[q];
        x[4*q] = t.x; x[4*q+1] = t.y; x[4*q+2] = t.z; x[4*q+3] = t.w;
    }

    float accP[64], accA[64];
    #pragma unroll
    for (int j = 0; j < 64; j++) { accP[j] = 0.f; accA[j] = 0.f; }
    #pragma unroll 4
    for (int i = 0; i < 64; i++) {
        const float xi = x[i];
        #pragma unroll
        for (int j = 0; j < 64; j++) {
            accP[j] = fmaf(xi, sW1[i*64+j], accP[j]);
            accA[j] = fmaf(xi, sA1[i*64+j], accA[j]);
        }
    }
    float4* Pv = reinterpret_cast<float4*>(g_P + (size_t)v * 64);
    float4* Av = reinterpret_cast<float4*>(g_A1B + (size_t)v * 64);
    #pragma unroll
    for (int q = 0; q < 16; q++) {
        Pv[q] = make_float4(accP[4*q], accP[4*q+1], accP[4*q+2], accP[4*q+3]);
        Av[q] = make_float4(accA[4*q], accA[4*q+1], accA[4*q+2], accA[4*q+3]);
    }
}

// ---------------------------------------------------------------------------
// Kernel 0b: split weights into B-fragment layout (bf16 hi/lo).
// B operand of m16n8k16 row.col: B[k][n] = W[k][n], fragment per lane:
//   reg0 = {W[k0][n], W[k0+1][n]},  reg1 = {W[k0+8][n], W[k0+9][n]}
//   with n = nt*8 + lane/4, k0 = kt*16 + (lane%4)*2
// ---------------------------------------------------------------------------
__global__ void __launch_bounds__(256) k_wfrag(const float* __restrict__ w2W,
                                               const float* __restrict__ a1W,
                                               const float* __restrict__ a2W)
{
    const int idx = blockIdx.x * 256 + threadIdx.x;   // over 3*4*8*32 = 3072
    if (idx >= 3072) return;
    const int lane = idx & 31;
    const int nt   = (idx >> 5) & 7;
    const int kt   = (idx >> 8) & 3;
    const int L    = idx >> 10;

    const float* W = (L == 0) ? w2W : (L == 1) ? a1W : a2W;
    const int n  = nt * 8 + (lane >> 2);
    const int k0 = kt * 16 + (lane & 3) * 2;

    const float w00 = W[(k0    ) * 64 + n];
    const float w01 = W[(k0 + 1) * 64 + n];
    const float w10 = W[(k0 + 8) * 64 + n];
    const float w11 = W[(k0 + 9) * 64 + n];

    u32 h0, l0, h1, l1;
    split2(w00, w01, h0, l0);
    split2(w10, w11, h1, l1);

    const int bhi = ((((L*2 + 0)*4 + kt)*8 + nt)*32 + lane)*2;
    const int blo = ((((L*2 + 1)*4 + kt)*8 + nt)*32 + lane)*2;
    g_Wf[bhi]     = h0;  g_Wf[bhi + 1] = h1;
    g_Wf[blo]     = l0;  g_Wf[blo + 1] = l1;
}

// ---------------------------------------------------------------------------
// 64->64 GEMM layer on one warp tile (16 rows), D += A@W via 3-term bf16 split
// sBFL points at this layer's fragment block: [part:2][kt:4][nt:8][lane:32][2]
// ---------------------------------------------------------------------------
__device__ __forceinline__ void gemm64(float* D, const u32* ah, const u32* al,
                                       const u32* sBFL, int lane)
{
    #pragma unroll
    for (int nt = 0; nt < 8; nt++) {
        float d0 = 0.f, d1 = 0.f, d2 = 0.f, d3 = 0.f;
        #pragma unroll
        for (int kt = 0; kt < 4; kt++) {
            const u32* bp = sBFL + (kt*8 + nt)*64 + lane*2;
            const uint2 bh = *reinterpret_cast<const uint2*>(bp);
            const uint2 bl = *reinterpret_cast<const uint2*>(bp + 2048);
            mma16816(d0,d1,d2,d3, ah[kt*4],ah[kt*4+1],ah[kt*4+2],ah[kt*4+3], bh.x,bh.y);
            mma16816(d0,d1,d2,d3, al[kt*4],al[kt*4+1],al[kt*4+2],al[kt*4+3], bh.x,bh.y);
            mma16816(d0,d1,d2,d3, ah[kt*4],ah[kt*4+1],ah[kt*4+2],ah[kt*4+3], bl.x,bl.y);
        }
        D[nt*4+0] = d0; D[nt*4+1] = d1; D[nt*4+2] = d2; D[nt*4+3] = d3;
    }
}

// ---------------------------------------------------------------------------
// Main kernel: layers 1..4 + scores, per warp-tile of 16 pairs.
// 256 threads = 8 warps = 128 pairs per iteration; persistent grid-stride.
// ---------------------------------------------------------------------------
#define DSM_U32  (12288 + 512 + 5*64)   // 13120 u32 = 52480 B
#define DSM_BYTES (DSM_U32 * 4)

__global__ void __launch_bounds__(256) k_main(
    const int*   __restrict__ nodes,
    const int*   __restrict__ nidx,
    const float* __restrict__ labels,
    const float* __restrict__ w1W,
    const float* __restrict__ w1b,
    const float* __restrict__ w2b,
    const float* __restrict__ a1b,
    const float* __restrict__ a2b,
    const float* __restrict__ a3W,
    const float* __restrict__ a3b)
{
    extern __shared__ u32 dsm[];
    u32*   sBF  = dsm;                       // 12288 u32 (48KB)
    float* sW1L = (float*)(dsm + 12288);     // 512
    float* sB1  = sW1L + 512;
    float* sB2  = sB1 + 64;
    float* sBa1 = sB2 + 64;
    float* sBa2 = sBa1 + 64;
    float* sA3  = sBa2 + 64;

    const int tid = threadIdx.x;
    {
        const uint4* src = reinterpret_cast<const uint4*>(g_Wf);
        uint4* dst = reinterpret_cast<uint4*>(sBF);
        for (int i = tid; i < 3072; i += 256) dst[i] = src[i];
        for (int i = tid; i < 512; i += 256) sW1L[i] = w1W[4096 + i];
        if (tid < 64) {
            sB1 [tid] = w1b[tid];
            sB2 [tid] = w2b[tid];
            sBa1[tid] = a1b[tid];
            sBa2[tid] = a2b[tid];
            sA3 [tid] = a3W[tid];
        }
    }
    __syncthreads();

    const float a3b0 = a3b[0];
    const int wid  = tid >> 5;
    const int lane = tid & 31;
    const int g    = lane >> 2;            // 0..7  (row within tile)
    const int q2   = (lane & 3) << 1;      // 0,2,4,6 (col pair base)

    for (int t = blockIdx.x; t < NTILE; t += gridDim.x) {
        const int p0 = t * 128 + wid * 16 + g;
        const int p1 = p0 + 8;

        u32 ah[16], al[16];                // A fragments [kt][slot]

        // ================= LAYER 1 (scalar) → A fragments =================
        #pragma unroll
        for (int rr = 0; rr < 2; rr++) {
            const int p  = rr ? p1 : p0;
            const int ni = __ldg(&nidx[p]);
            const float* Pr = g_P + (size_t)ni * 64;
            const float4* lv = reinterpret_cast<const float4*>(labels + (size_t)p * 8);
            const float4 la = lv[0], lb = lv[1];
            const float lab[8] = { la.x, la.y, la.z, la.w, lb.x, lb.y, lb.z, lb.w };

            #pragma unroll
            for (int kt = 0; kt < 4; kt++) {
                const int c0 = kt * 16 + q2;
                const float2 pa = *reinterpret_cast<const float2*>(Pr + c0);
                const float2 pb = *reinterpret_cast<const float2*>(Pr + c0 + 8);
                float v0 = pa.x + sB1[c0];
                float v1 = pa.y + sB1[c0 + 1];
                float v2 = pb.x + sB1[c0 + 8];
                float v3 = pb.y + sB1[c0 + 9];
                #pragma unroll
                for (int j = 0; j < 8; j++) {
                    const float* wr = sW1L + j * 64 + c0;
                    v0 = fmaf(lab[j], wr[0], v0);
                    v1 = fmaf(lab[j], wr[1], v1);
                    v2 = fmaf(lab[j], wr[8], v2);
                    v3 = fmaf(lab[j], wr[9], v3);
                }
                v0 = fmaxf(v0, 0.f); v1 = fmaxf(v1, 0.f);
                v2 = fmaxf(v2, 0.f); v3 = fmaxf(v3, 0.f);
                split2(v0, v1, ah[kt*4 + rr],     al[kt*4 + rr]);       // a0/a1
                split2(v2, v3, ah[kt*4 + 2 + rr], al[kt*4 + 2 + rr]);   // a2/a3
            }
        }

        float D[32];

        // ================= LAYER 2: o = relu(h @ W2 + b2) =================
        gemm64(D, ah, al, sBF, lane);
        #pragma unroll
        for (int nt = 0; nt < 8; nt++) {
            const int c0 = nt * 8 + q2;
            const float v0 = fmaxf(D[nt*4+0] + sB2[c0],     0.f);
            const float v1 = fmaxf(D[nt*4+1] + sB2[c0 + 1], 0.f);
            const float v2 = fmaxf(D[nt*4+2] + sB2[c0],     0.f);
            const float v3 = fmaxf(D[nt*4+3] + sB2[c0 + 1], 0.f);
            *reinterpret_cast<float2*>(g_O + (size_t)p0 * 64 + c0) = make_float2(v0, v1);
            *reinterpret_cast<float2*>(g_O + (size_t)p1 * 64 + c0) = make_float2(v2, v3);
            const int kt = nt >> 1, hf = nt & 1;
            split2(v0, v1, ah[kt*4 + hf*2 + 0], al[kt*4 + hf*2 + 0]);
            split2(v2, v3, ah[kt*4 + hf*2 + 1], al[kt*4 + hf*2 + 1]);
        }

        // ============ LAYER 3: a = relu(o @ A1a + A1B[node] + b) ==========
        const int node0 = __ldg(&nodes[p0 / K_N]);
        const int node1 = __ldg(&nodes[p1 / K_N]);
        const float* G0 = g_A1B + (size_t)node0 * 64;
        const float* G1 = g_A1B + (size_t)node1 * 64;

        gemm64(D, ah, al, sBF + 4096, lane);
        #pragma unroll
        for (int nt = 0; nt < 8; nt++) {
            const int c0 = nt * 8 + q2;
            const float2 g0 = *reinterpret_cast<const float2*>(G0 + c0);
            const float2 g1 = *reinterpret_cast<const float2*>(G1 + c0);
            const float v0 = fmaxf(D[nt*4+0] + sBa1[c0]     + g0.x, 0.f);
            const float v1 = fmaxf(D[nt*4+1] + sBa1[c0 + 1] + g0.y, 0.f);
            const float v2 = fmaxf(D[nt*4+2] + sBa1[c0]     + g1.x, 0.f);
            const float v3 = fmaxf(D[nt*4+3] + sBa1[c0 + 1] + g1.y, 0.f);
            const int kt = nt >> 1, hf = nt & 1;
            split2(v0, v1, ah[kt*4 + hf*2 + 0], al[kt*4 + hf*2 + 0]);
            split2(v2, v3, ah[kt*4 + hf*2 + 1], al[kt*4 + hf*2 + 1]);
        }

        // ========= LAYER 4: a2 = relu(a @ A2 + b); score = a2 . a3 ========
        gemm64(D, ah, al, sBF + 8192, lane);
        float s0 = 0.f, s1 = 0.f;
        #pragma unroll
        for (int nt = 0; nt < 8; nt++) {
            const int c0 = nt * 8 + q2;
            const float v0 = fmaxf(D[nt*4+0] + sBa2[c0],     0.f);
            const float v1 = fmaxf(D[nt*4+1] + sBa2[c0 + 1], 0.f);
            const float v2 = fmaxf(D[nt*4+2] + sBa2[c0],     0.f);
            const float v3 = fmaxf(D[nt*4+3] + sBa2[c0 + 1], 0.f);
            s0 = fmaf(v0, sA3[c0], s0);
            s0 = fmaf(v1, sA3[c0 + 1], s0);
            s1 = fmaf(v2, sA3[c0], s1);
            s1 = fmaf(v3, sA3[c0 + 1], s1);
        }
        s0 += __shfl_xor_sync(0xffffffffu, s0, 1);
        s0 += __shfl_xor_sync(0xffffffffu, s0, 2);
        s1 += __shfl_xor_sync(0xffffffffu, s1, 1);
        s1 += __shfl_xor_sync(0xffffffffu, s1, 2);
        if ((lane & 3) == 0) {
            g_S[p0] = s0 + a3b0;
            g_S[p1] = s1 + a3b0;
        }
    }
}

// ---------------------------------------------------------------------------
// Kernel 3: masked softmax over K neighbors + weighted aggregate (verified)
// ---------------------------------------------------------------------------
__global__ void __launch_bounds__(256) k_agg(const int*   __restrict__ nodes,
                                             const int*   __restrict__ nlen,
                                             const float* __restrict__ u2e,
                                             float*       __restrict__ out)
{
    const int wid  = (blockIdx.x * 256 + threadIdx.x) >> 5;
    const int lane = threadIdx.x & 31;
    if (wid >= B_N) return;
    const int b   = wid;
    const int len = nlen[b];

    if (len <= 0) {
        const int node = nodes[b];
        const float2* src = reinterpret_cast<const float2*>(u2e + (size_t)node * 64);
        reinterpret_cast<float2*>(out + (size_t)b * 64)[lane] = src[lane];
        return;
    }

    const float* Sb = g_S + (size_t)b * K_N;
    float s0 = (lane      < len) ? Sb[lane]      : -3.0e38f;
    float s1 = (lane + 32 < len) ? Sb[lane + 32] : -3.0e38f;

    float m = fmaxf(s0, s1);
    #pragma unroll
    for (int o = 16; o > 0; o >>= 1) m = fmaxf(m, __shfl_xor_sync(0xffffffffu, m, o));

    const float e0 = (lane      < len) ? expf(s0 - m) : 0.f;
    const float e1 = (lane + 32 < len) ? expf(s1 - m) : 0.f;

    float ss = e0 + e1;
    #pragma unroll
    for (int o = 16; o > 0; o >>= 1) ss += __shfl_xor_sync(0xffffffffu, ss, o);

    const float inv = 1.f / ss;
    const float w0 = e0 * inv;
    const float w1 = e1 * inv;

    float2 agg = make_float2(0.f, 0.f);
    const float2* Ob = reinterpret_cast<const float2*>(g_O + (size_t)b * K_N * 64);
    for (int k = 0; k < len; k++) {
        const float ak = (k < 32) ? __shfl_sync(0xffffffffu, w0, k)
                                  : __shfl_sync(0xffffffffu, w1, k - 32);
        const float2 ov = Ob[k * 32 + lane];
        agg.x = fmaf(ak, ov.x, agg.x);
        agg.y = fmaf(ak, ov.y, agg.y);
    }
    reinterpret_cast<float2*>(out + (size_t)b * 64)[lane] = agg;
}

// ---------------------------------------------------------------------------
// kernel_launch
// ---------------------------------------------------------------------------
extern "C" void kernel_launch(void* const* d_in, const int* in_sizes, int n_in,
                              void* d_out, int out_size)
{
    const int*   nodes  = (const int*)  d_in[0];
    const int*   nidx   = (const int*)  d_in[1];
    const int*   nlen   = (const int*)  d_in[2];
    const float* labels = (const float*)d_in[3];
    const float* u2e    = (const float*)d_in[4];
    const float* w1W    = (const float*)d_in[5];
    const float* w1b    = (const float*)d_in[6];
    const float* w2W    = (const float*)d_in[7];
    const float* w2b    = (const float*)d_in[8];
    const float* a1W    = (const float*)d_in[9];
    const float* a1b    = (const float*)d_in[10];
    const float* a2W    = (const float*)d_in[11];
    const float* a2b    = (const float*)d_in[12];
    const float* a3W    = (const float*)d_in[13];
    const float* a3b    = (const float*)d_in[14];
    float* out = (float*)d_out;

    cudaFuncSetAttribute(k_main, cudaFuncAttributeMaxDynamicSharedMemorySize, DSM_BYTES);

    k_pre  <<<(V_N + 127) / 128, 128>>>(u2e, w1W, a1W);
    k_wfrag<<<12, 256>>>(w2W, a1W, a2W);
    k_main <<<296, 256, DSM_BYTES>>>(nodes, nidx, labels, w1W, w1b,
                                     w2b, a1b, a2b, a3W, a3b);
    k_agg  <<<(B_N * 32 + 255) / 256, 256>>>(nodes, nlen, u2e, out);
}

// round 6
// speedup vs baseline: 4.2527x; 1.1961x over previous
#include <cuda_runtime.h>
#include <cuda_bf16.h>
#include <cstdint>
#include <math.h>

// Problem constants
#define B_N   16384
#define K_N   50
#define V_N   100000
#define BK_N  (B_N * K_N)          // 819200
#define NTILE (BK_N / 128)         // 6400 tiles of 128 pairs
#define VTILE (V_N / 16)           // 6250 vocab warp-tiles (exact)

typedef unsigned int u32;

// ---------------------------------------------------------------------------
// Device scratch (static — no cudaMalloc allowed)
// ---------------------------------------------------------------------------
__device__ float g_P  [(size_t)V_N * 64];      // u2e @ w1_W[0:64,:]
__device__ float g_A1B[(size_t)V_N * 64];      // u2e @ a1_W[64:128,:]
__device__ float g_O  [(size_t)BK_N * 64];     // o_history (fp32)
__device__ float g_S  [(size_t)BK_N];          // attention scores
// Weight fragments: [L:5][part:2][kt:4][nt:8][lane:32][reg:2] u32 (bf16x2)
// L: 0=w2W  1=a1W[0:64]  2=a2W  3=w1W[0:64]  4=a1W[64:128]
__device__ u32   g_Wf [5 * 4096];              // 80KB

// ---------------------------------------------------------------------------
// bf16 helpers
// ---------------------------------------------------------------------------
__device__ __forceinline__ u32 pack_bf16x2(float lo, float hi) {
    u32 d;
    asm("cvt.rn.bf16x2.f32 %0, %1, %2;" : "=r"(d) : "f"(hi), "f"(lo));
    return d;
}
// Split two f32 into packed bf16x2 hi part + bf16x2 residual (lo) part.
__device__ __forceinline__ void split2(float v0, float v1, u32& h, u32& l) {
    h = pack_bf16x2(v0, v1);
    const float r0 = v0 - __uint_as_float(h << 16);
    const float r1 = v1 - __uint_as_float(h & 0xFFFF0000u);
    l = pack_bf16x2(r0, r1);
}
// m16n8k16 row.col bf16 MMA, fp32 accumulate (sm_80+ baseline)
__device__ __forceinline__ void mma16816(float& d0, float& d1, float& d2, float& d3,
                                         u32 a0, u32 a1, u32 a2, u32 a3,
                                         u32 b0, u32 b1) {
    asm("mma.sync.aligned.m16n8k16.row.col.f32.bf16.bf16.f32 "
        "{%0,%1,%2,%3}, {%4,%5,%6,%7}, {%8,%9}, {%0,%1,%2,%3};"
        : "+f"(d0), "+f"(d1), "+f"(d2), "+f"(d3)
        : "r"(a0), "r"(a1), "r"(a2), "r"(a3), "r"(b0), "r"(b1));
}

// ---------------------------------------------------------------------------
// Kernel 0: split weights into B-fragment layout (bf16 hi/lo), 5 matrices.
// B fragment (m16n8k16 row.col): n = nt*8 + lane/4, k0 = kt*16 + (lane%4)*2
//   reg0 = {W[k0][n], W[k0+1][n]},  reg1 = {W[k0+8][n], W[k0+9][n]}
// ---------------------------------------------------------------------------
__global__ void __launch_bounds__(256) k_wfrag(const float* __restrict__ w2W,
                                               const float* __restrict__ a1W,
                                               const float* __restrict__ a2W,
                                               const float* __restrict__ w1W)
{
    const int idx = blockIdx.x * 256 + threadIdx.x;   // over 5*4*8*32 = 5120
    if (idx >= 5120) return;
    const int lane = idx & 31;
    const int nt   = (idx >> 5) & 7;
    const int kt   = (idx >> 8) & 3;
    const int L    = idx >> 10;

    const float* W;
    if (L == 0)      W = w2W;
    else if (L == 1) W = a1W;
    else if (L == 2) W = a2W;
    else if (L == 3) W = w1W;
    else             W = a1W + 4096;    // rows 64..127

    const int n  = nt * 8 + (lane >> 2);
    const int k0 = kt * 16 + (lane & 3) * 2;

    const float w00 = W[(k0    ) * 64 + n];
    const float w01 = W[(k0 + 1) * 64 + n];
    const float w10 = W[(k0 + 8) * 64 + n];
    const float w11 = W[(k0 + 9) * 64 + n];

    u32 h0, l0, h1, l1;
    split2(w00, w01, h0, l0);
    split2(w10, w11, h1, l1);

    const int base = L * 4096;
    const int fhi = base + (((kt)*8 + nt)*32 + lane)*2;          // part 0
    const int flo = base + 2048 + (((kt)*8 + nt)*32 + lane)*2;   // part 1
    g_Wf[fhi]     = h0;  g_Wf[fhi + 1] = h1;
    g_Wf[flo]     = l0;  g_Wf[flo + 1] = l1;
}

// ---------------------------------------------------------------------------
// 64->64 GEMM layer on one warp tile (16 rows), D = A@W via 3-term bf16 split
// sBFL: this layer's fragment block [part:2][kt:4][nt:8][lane:32][2]
// ---------------------------------------------------------------------------
__device__ __forceinline__ void gemm64(float* D, const u32* ah, const u32* al,
                                       const u32* sBFL, int lane)
{
    #pragma unroll
    for (int nt = 0; nt < 8; nt++) {
        float d0 = 0.f, d1 = 0.f, d2 = 0.f, d3 = 0.f;
        #pragma unroll
        for (int kt = 0; kt < 4; kt++) {
            const u32* bp = sBFL + (kt*8 + nt)*64 + lane*2;
            const uint2 bh = *reinterpret_cast<const uint2*>(bp);
            const uint2 bl = *reinterpret_cast<const uint2*>(bp + 2048);
            mma16816(d0,d1,d2,d3, ah[kt*4],ah[kt*4+1],ah[kt*4+2],ah[kt*4+3], bh.x,bh.y);
            mma16816(d0,d1,d2,d3, al[kt*4],al[kt*4+1],al[kt*4+2],al[kt*4+3], bh.x,bh.y);
            mma16816(d0,d1,d2,d3, ah[kt*4],ah[kt*4+1],ah[kt*4+2],ah[kt*4+3], bl.x,bl.y);
        }
        D[nt*4+0] = d0; D[nt*4+1] = d1; D[nt*4+2] = d2; D[nt*4+3] = d3;
    }
}

// Build A fragments (hi/lo) for rows r0, r0+8 of a row-major [*,64] fp32 matrix.
__device__ __forceinline__ void load_a_frags(const float* M, int r0,
                                             int q2, u32* ah, u32* al)
{
    #pragma unroll
    for (int rr = 0; rr < 2; rr++) {
        const float* Mr = M + (size_t)(r0 + rr * 8) * 64;
        #pragma unroll
        for (int kt = 0; kt < 4; kt++) {
            const int c0 = kt * 16 + q2;
            const float2 pa = *reinterpret_cast<const float2*>(Mr + c0);
            const float2 pb = *reinterpret_cast<const float2*>(Mr + c0 + 8);
            split2(pa.x, pa.y, ah[kt*4 + rr],     al[kt*4 + rr]);
            split2(pb.x, pb.y, ah[kt*4 + 2 + rr], al[kt*4 + 2 + rr]);
        }
    }
}

// ---------------------------------------------------------------------------
// Kernel 1: HMMA per-vocab precompute of P and A1B.
// 256 threads = 8 warps, each warp handles 16 vocab rows.
// ---------------------------------------------------------------------------
__global__ void __launch_bounds__(256) k_pre(const float* __restrict__ u2e)
{
    __shared__ u32 sBF[8192];        // L=3 (W1) and L=4 (A1Bw) frag blocks, 32KB

    const int tid = threadIdx.x;
    {
        const uint4* src = reinterpret_cast<const uint4*>(g_Wf + 3 * 4096);
        uint4* dst = reinterpret_cast<uint4*>(sBF);
        for (int i = tid; i < 2048; i += 256) dst[i] = src[i];
    }
    __syncthreads();

    const int wid  = tid >> 5;
    const int lane = tid & 31;
    const int g    = lane >> 2;
    const int q2   = (lane & 3) << 1;

    const int wt = blockIdx.x * 8 + wid;
    if (wt >= VTILE) return;
    const int v0 = wt * 16 + g;
    const int v1 = v0 + 8;

    u32 ah[16], al[16];
    load_a_frags(u2e, wt * 16 + g, q2, ah, al);

    float D[32];

    // P = u2e @ W1[0:64]
    gemm64(D, ah, al, sBF, lane);
    #pragma unroll
    for (int nt = 0; nt < 8; nt++) {
        const int c0 = nt * 8 + q2;
        *reinterpret_cast<float2*>(g_P + (size_t)v0 * 64 + c0) = make_float2(D[nt*4+0], D[nt*4+1]);
        *reinterpret_cast<float2*>(g_P + (size_t)v1 * 64 + c0) = make_float2(D[nt*4+2], D[nt*4+3]);
    }

    // A1B = u2e @ a1_W[64:128]
    gemm64(D, ah, al, sBF + 4096, lane);
    #pragma unroll
    for (int nt = 0; nt < 8; nt++) {
        const int c0 = nt * 8 + q2;
        *reinterpret_cast<float2*>(g_A1B + (size_t)v0 * 64 + c0) = make_float2(D[nt*4+0], D[nt*4+1]);
        *reinterpret_cast<float2*>(g_A1B + (size_t)v1 * 64 + c0) = make_float2(D[nt*4+2], D[nt*4+3]);
    }
}

// ---------------------------------------------------------------------------
// Main kernel: layers 1..4 + scores, per warp-tile of 16 pairs.
// ---------------------------------------------------------------------------
#define DSM_U32  (12288 + 512 + 5*64)   // 13120 u32 = 52480 B
#define DSM_BYTES (DSM_U32 * 4)

__global__ void __launch_bounds__(256) k_main(
    const int*   __restrict__ nodes,
    const int*   __restrict__ nidx,
    const float* __restrict__ labels,
    const float* __restrict__ w1W,
    const float* __restrict__ w1b,
    const float* __restrict__ w2b,
    const float* __restrict__ a1b,
    const float* __restrict__ a2b,
    const float* __restrict__ a3W,
    const float* __restrict__ a3b)
{
    extern __shared__ u32 dsm[];
    u32*   sBF  = dsm;                       // 12288 u32 (48KB): L=0,1,2
    float* sW1L = (float*)(dsm + 12288);     // 512
    float* sB1  = sW1L + 512;
    float* sB2  = sB1 + 64;
    float* sBa1 = sB2 + 64;
    float* sBa2 = sBa1 + 64;
    float* sA3  = sBa2 + 64;

    const int tid = threadIdx.x;
    {
        const uint4* src = reinterpret_cast<const uint4*>(g_Wf);
        uint4* dst = reinterpret_cast<uint4*>(sBF);
        for (int i = tid; i < 3072; i += 256) dst[i] = src[i];
        for (int i = tid; i < 512; i += 256) sW1L[i] = w1W[4096 + i];
        if (tid < 64) {
            sB1 [tid] = w1b[tid];
            sB2 [tid] = w2b[tid];
            sBa1[tid] = a1b[tid];
            sBa2[tid] = a2b[tid];
            sA3 [tid] = a3W[tid];
        }
    }
    __syncthreads();

    const float a3b0 = a3b[0];
    const int wid  = tid >> 5;
    const int lane = tid & 31;
    const int g    = lane >> 2;            // 0..7  (row within tile)
    const int q2   = (lane & 3) << 1;      // 0,2,4,6 (col pair base)

    for (int t = blockIdx.x; t < NTILE; t += gridDim.x) {
        const int p0 = t * 128 + wid * 16 + g;
        const int p1 = p0 + 8;

        u32 ah[16], al[16];                // A fragments [kt][slot]

        // ================= LAYER 1 (scalar) → A fragments =================
        #pragma unroll
        for (int rr = 0; rr < 2; rr++) {
            const int p  = rr ? p1 : p0;
            const int ni = __ldg(&nidx[p]);
            const float* Pr = g_P + (size_t)ni * 64;
            const float4* lv = reinterpret_cast<const float4*>(labels + (size_t)p * 8);
            const float4 la = lv[0], lb = lv[1];
            const float lab[8] = { la.x, la.y, la.z, la.w, lb.x, lb.y, lb.z, lb.w };

            #pragma unroll
            for (int kt = 0; kt < 4; kt++) {
                const int c0 = kt * 16 + q2;
                const float2 pa = *reinterpret_cast<const float2*>(Pr + c0);
                const float2 pb = *reinterpret_cast<const float2*>(Pr + c0 + 8);
                float v0 = pa.x + sB1[c0];
                float v1 = pa.y + sB1[c0 + 1];
                float v2 = pb.x + sB1[c0 + 8];
                float v3 = pb.y + sB1[c0 + 9];
                #pragma unroll
                for (int j = 0; j < 8; j++) {
                    const float* wr = sW1L + j * 64 + c0;
                    v0 = fmaf(lab[j], wr[0], v0);
                    v1 = fmaf(lab[j], wr[1], v1);
                    v2 = fmaf(lab[j], wr[8], v2);
                    v3 = fmaf(lab[j], wr[9], v3);
                }
                v0 = fmaxf(v0, 0.f); v1 = fmaxf(v1, 0.f);
                v2 = fmaxf(v2, 0.f); v3 = fmaxf(v3, 0.f);
                split2(v0, v1, ah[kt*4 + rr],     al[kt*4 + rr]);
                split2(v2, v3, ah[kt*4 + 2 + rr], al[kt*4 + 2 + rr]);
            }
        }

        float D[32];

        // ================= LAYER 2: o = relu(h @ W2 + b2) =================
        gemm64(D, ah, al, sBF, lane);
        #pragma unroll
        for (int nt = 0; nt < 8; nt++) {
            const int c0 = nt * 8 + q2;
            const float v0 = fmaxf(D[nt*4+0] + sB2[c0],     0.f);
            const float v1 = fmaxf(D[nt*4+1] + sB2[c0 + 1], 0.f);
            const float v2 = fmaxf(D[nt*4+2] + sB2[c0],     0.f);
            const float v3 = fmaxf(D[nt*4+3] + sB2[c0 + 1], 0.f);
            *reinterpret_cast<float2*>(g_O + (size_t)p0 * 64 + c0) = make_float2(v0, v1);
            *reinterpret_cast<float2*>(g_O + (size_t)p1 * 64 + c0) = make_float2(v2, v3);
            const int kt = nt >> 1, hf = nt & 1;
            split2(v0, v1, ah[kt*4 + hf*2 + 0], al[kt*4 + hf*2 + 0]);
            split2(v2, v3, ah[kt*4 + hf*2 + 1], al[kt*4 + hf*2 + 1]);
        }

        // ============ LAYER 3: a = relu(o @ A1a + A1B[node] + b) ==========
        const int node0 = __ldg(&nodes[p0 / K_N]);
        const int node1 = __ldg(&nodes[p1 / K_N]);
        const float* G0 = g_A1B + (size_t)node0 * 64;
        const float* G1 = g_A1B + (size_t)node1 * 64;

        gemm64(D, ah, al, sBF + 4096, lane);
        #pragma unroll
        for (int nt = 0; nt < 8; nt++) {
            const int c0 = nt * 8 + q2;
            const float2 g0 = *reinterpret_cast<const float2*>(G0 + c0);
            const float2 g1 = *reinterpret_cast<const float2*>(G1 + c0);
            const float v0 = fmaxf(D[nt*4+0] + sBa1[c0]     + g0.x, 0.f);
            const float v1 = fmaxf(D[nt*4+1] + sBa1[c0 + 1] + g0.y, 0.f);
            const float v2 = fmaxf(D[nt*4+2] + sBa1[c0]     + g1.x, 0.f);
            const float v3 = fmaxf(D[nt*4+3] + sBa1[c0 + 1] + g1.y, 0.f);
            const int kt = nt >> 1, hf = nt & 1;
            split2(v0, v1, ah[kt*4 + hf*2 + 0], al[kt*4 + hf*2 + 0]);
            split2(v2, v3, ah[kt*4 + hf*2 + 1], al[kt*4 + hf*2 + 1]);
        }

        // ========= LAYER 4: a2 = relu(a @ A2 + b); score = a2 . a3 ========
        gemm64(D, ah, al, sBF + 8192, lane);
        float s0 = 0.f, s1 = 0.f;
        #pragma unroll
        for (int nt = 0; nt < 8; nt++) {
            const int c0 = nt * 8 + q2;
            const float v0 = fmaxf(D[nt*4+0] + sBa2[c0],     0.f);
            const float v1 = fmaxf(D[nt*4+1] + sBa2[c0 + 1], 0.f);
            const float v2 = fmaxf(D[nt*4+2] + sBa2[c0],     0.f);
            const float v3 = fmaxf(D[nt*4+3] + sBa2[c0 + 1], 0.f);
            s0 = fmaf(v0, sA3[c0], s0);
            s0 = fmaf(v1, sA3[c0 + 1], s0);
            s1 = fmaf(v2, sA3[c0], s1);
            s1 = fmaf(v3, sA3[c0 + 1], s1);
        }
        s0 += __shfl_xor_sync(0xffffffffu, s0, 1);
        s0 += __shfl_xor_sync(0xffffffffu, s0, 2);
        s1 += __shfl_xor_sync(0xffffffffu, s1, 1);
        s1 += __shfl_xor_sync(0xffffffffu, s1, 2);
        if ((lane & 3) == 0) {
            g_S[p0] = s0 + a3b0;
            g_S[p1] = s1 + a3b0;
        }
    }
}

// ---------------------------------------------------------------------------
// Kernel 3: masked softmax over K neighbors + weighted aggregate
// ---------------------------------------------------------------------------
__global__ void __launch_bounds__(256) k_agg(const int*   __restrict__ nodes,
                                             const int*   __restrict__ nlen,
                                             const float* __restrict__ u2e,
                                             float*       __restrict__ out)
{
    const int wid  = (blockIdx.x * 256 + threadIdx.x) >> 5;
    const int lane = threadIdx.x & 31;
    if (wid >= B_N) return;
    const int b   = wid;
    const int len = nlen[b];

    if (len <= 0) {
        const int node = nodes[b];
        const float2* src = reinterpret_cast<const float2*>(u2e + (size_t)node * 64);
        reinterpret_cast<float2*>(out + (size_t)b * 64)[lane] = src[lane];
        return;
    }

    const float* Sb = g_S + (size_t)b * K_N;
    float s0 = (lane      < len) ? Sb[lane]      : -3.0e38f;
    float s1 = (lane + 32 < len) ? Sb[lane + 32] : -3.0e38f;

    float m = fmaxf(s0, s1);
    #pragma unroll
    for (int o = 16; o > 0; o >>= 1) m = fmaxf(m, __shfl_xor_sync(0xffffffffu, m, o));

    const float e0 = (lane      < len) ? expf(s0 - m) : 0.f;
    const float e1 = (lane + 32 < len) ? expf(s1 - m) : 0.f;

    float ss = e0 + e1;
    #pragma unroll
    for (int o = 16; o > 0; o >>= 1) ss += __shfl_xor_sync(0xffffffffu, ss, o);

    const float inv = 1.f / ss;
    const float w0 = e0 * inv;
    const float w1 = e1 * inv;

    float2 agg = make_float2(0.f, 0.f);
    const float2* Ob = reinterpret_cast<const float2*>(g_O + (size_t)b * K_N * 64);
    #pragma unroll 4
    for (int k = 0; k < len; k++) {
        const float ak = (k < 32) ? __shfl_sync(0xffffffffu, w0, k)
                                  : __shfl_sync(0xffffffffu, w1, k - 32);
        const float2 ov = Ob[k * 32 + lane];
        agg.x = fmaf(ak, ov.x, agg.x);
        agg.y = fmaf(ak, ov.y, agg.y);
    }
    reinterpret_cast<float2*>(out + (size_t)b * 64)[lane] = agg;
}

// ---------------------------------------------------------------------------
// kernel_launch
// ---------------------------------------------------------------------------
extern "C" void kernel_launch(void* const* d_in, const int* in_sizes, int n_in,
                              void* d_out, int out_size)
{
    const int*   nodes  = (const int*)  d_in[0];
    const int*   nidx   = (const int*)  d_in[1];
    const int*   nlen   = (const int*)  d_in[2];
    const float* labels = (const float*)d_in[3];
    const float* u2e    = (const float*)d_in[4];
    const float* w1W    = (const float*)d_in[5];
    const float* w1b    = (const float*)d_in[6];
    const float* w2W    = (const float*)d_in[7];
    const float* w2b    = (const float*)d_in[8];
    const float* a1W    = (const float*)d_in[9];
    const float* a1b    = (const float*)d_in[10];
    const float* a2W    = (const float*)d_in[11];
    const float* a2b    = (const float*)d_in[12];
    const float* a3W    = (const float*)d_in[13];
    const float* a3b    = (const float*)d_in[14];
    float* out = (float*)d_out;

    cudaFuncSetAttribute(k_main, cudaFuncAttributeMaxDynamicSharedMemorySize, DSM_BYTES);

    k_wfrag<<<20, 256>>>(w2W, a1W, a2W, w1W);
    k_pre  <<<(VTILE + 7) / 8, 256>>>(u2e);
    k_main <<<296, 256, DSM_BYTES>>>(nodes, nidx, labels, w1W, w1b,
                                     w2b, a1b, a2b, a3W, a3b);
    k_agg  <<<(B_N * 32 + 255) / 256, 256>>>(nodes, nlen, u2e, out);
}

// round 7
// speedup vs baseline: 4.3541x; 1.0238x over previous
#include <cuda_runtime.h>
#include <cuda_bf16.h>
#include <cstdint>
#include <math.h>

// Problem constants
#define B_N   16384
#define K_N   50
#define V_N   100000
#define BK_N  (B_N * K_N)          // 819200
#define NTILE (BK_N / 128)         // 6400 tiles of 128 pairs
#define VTILE (V_N / 16)           // 6250 vocab warp-tiles (exact)

typedef unsigned int u32;

// ---------------------------------------------------------------------------
// Device scratch (static — no cudaMalloc allowed)
// ---------------------------------------------------------------------------
__device__ float g_P  [(size_t)V_N * 64];      // u2e @ w1_W[0:64,:]
__device__ float g_A1B[(size_t)V_N * 64];      // u2e @ a1_W[64:128,:]
__device__ float g_O  [(size_t)BK_N * 64];     // o_history (fp32)
__device__ float g_S  [(size_t)BK_N];          // attention scores
// Weight fragments: [L:5][part:2][kt:4][nt:8][lane:32][reg:2] u32 (bf16x2)
// L: 0=w2W  1=a1W[0:64]  2=a2W  3=w1W[0:64]  4=a1W[64:128]
__device__ u32   g_Wf [5 * 4096];              // 80KB

// ---------------------------------------------------------------------------
// bf16 helpers
// ---------------------------------------------------------------------------
__device__ __forceinline__ u32 pack_bf16x2(float lo, float hi) {
    u32 d;
    asm("cvt.rn.bf16x2.f32 %0, %1, %2;" : "=r"(d) : "f"(hi), "f"(lo));
    return d;
}
// Split two f32 into packed bf16x2 hi part + bf16x2 residual (lo) part.
__device__ __forceinline__ void split2(float v0, float v1, u32& h, u32& l) {
    h = pack_bf16x2(v0, v1);
    const float r0 = v0 - __uint_as_float(h << 16);
    const float r1 = v1 - __uint_as_float(h & 0xFFFF0000u);
    l = pack_bf16x2(r0, r1);
}
// m16n8k16 row.col bf16 MMA, fp32 accumulate (sm_80+ baseline)
__device__ __forceinline__ void mma16816(float& d0, float& d1, float& d2, float& d3,
                                         u32 a0, u32 a1, u32 a2, u32 a3,
                                         u32 b0, u32 b1) {
    asm("mma.sync.aligned.m16n8k16.row.col.f32.bf16.bf16.f32 "
        "{%0,%1,%2,%3}, {%4,%5,%6,%7}, {%8,%9}, {%0,%1,%2,%3};"
        : "+f"(d0), "+f"(d1), "+f"(d2), "+f"(d3)
        : "r"(a0), "r"(a1), "r"(a2), "r"(a3), "r"(b0), "r"(b1));
}

// ---------------------------------------------------------------------------
// Kernel 0: split weights into B-fragment layout (bf16 hi/lo), 5 matrices.
// ---------------------------------------------------------------------------
__global__ void __launch_bounds__(256) k_wfrag(const float* __restrict__ w2W,
                                               const float* __restrict__ a1W,
                                               const float* __restrict__ a2W,
                                               const float* __restrict__ w1W)
{
    const int idx = blockIdx.x * 256 + threadIdx.x;   // over 5*4*8*32 = 5120
    if (idx >= 5120) return;
    const int lane = idx & 31;
    const int nt   = (idx >> 5) & 7;
    const int kt   = (idx >> 8) & 3;
    const int L    = idx >> 10;

    const float* W;
    if (L == 0)      W = w2W;
    else if (L == 1) W = a1W;
    else if (L == 2) W = a2W;
    else if (L == 3) W = w1W;
    else             W = a1W + 4096;    // rows 64..127

    const int n  = nt * 8 + (lane >> 2);
    const int k0 = kt * 16 + (lane & 3) * 2;

    const float w00 = W[(k0    ) * 64 + n];
    const float w01 = W[(k0 + 1) * 64 + n];
    const float w10 = W[(k0 + 8) * 64 + n];
    const float w11 = W[(k0 + 9) * 64 + n];

    u32 h0, l0, h1, l1;
    split2(w00, w01, h0, l0);
    split2(w10, w11, h1, l1);

    const int base = L * 4096;
    const int fhi = base + (((kt)*8 + nt)*32 + lane)*2;          // part 0
    const int flo = base + 2048 + (((kt)*8 + nt)*32 + lane)*2;   // part 1
    g_Wf[fhi]     = h0;  g_Wf[fhi + 1] = h1;
    g_Wf[flo]     = l0;  g_Wf[flo + 1] = l1;
}

// ---------------------------------------------------------------------------
// Single-tile 64->64 GEMM (M=16), used by k_pre.
// ---------------------------------------------------------------------------
__device__ __forceinline__ void gemm64(float* D, const u32* ah, const u32* al,
                                       const u32* sBFL, int lane)
{
    #pragma unroll
    for (int nt = 0; nt < 8; nt++) {
        float d0 = 0.f, d1 = 0.f, d2 = 0.f, d3 = 0.f;
        #pragma unroll
        for (int kt = 0; kt < 4; kt++) {
            const u32* bp = sBFL + (kt*8 + nt)*64 + lane*2;
            const uint2 bh = *reinterpret_cast<const uint2*>(bp);
            const uint2 bl = *reinterpret_cast<const uint2*>(bp + 2048);
            mma16816(d0,d1,d2,d3, ah[kt*4],ah[kt*4+1],ah[kt*4+2],ah[kt*4+3], bh.x,bh.y);
            mma16816(d0,d1,d2,d3, al[kt*4],al[kt*4+1],al[kt*4+2],al[kt*4+3], bh.x,bh.y);
            mma16816(d0,d1,d2,d3, ah[kt*4],ah[kt*4+1],ah[kt*4+2],ah[kt*4+3], bl.x,bl.y);
        }
        D[nt*4+0] = d0; D[nt*4+1] = d1; D[nt*4+2] = d2; D[nt*4+3] = d3;
    }
}

// Dual-tile 64->64 GEMM (M=32): two A tiles share each B-fragment load.
__device__ __forceinline__ void gemm64x2(float* D,
                                         const u32* ahA, const u32* alA,
                                         const u32* ahB, const u32* alB,
                                         const u32* sBFL, int lane)
{
    #pragma unroll
    for (int nt = 0; nt < 8; nt++) {
        float d0=0.f,d1=0.f,d2=0.f,d3=0.f,d4=0.f,d5=0.f,d6=0.f,d7=0.f;
        #pragma unroll
        for (int kt = 0; kt < 4; kt++) {
            const u32* bp = sBFL + (kt*8 + nt)*64 + lane*2;
            const uint2 bh = *reinterpret_cast<const uint2*>(bp);
            const uint2 bl = *reinterpret_cast<const uint2*>(bp + 2048);
            mma16816(d0,d1,d2,d3, ahA[kt*4],ahA[kt*4+1],ahA[kt*4+2],ahA[kt*4+3], bh.x,bh.y);
            mma16816(d0,d1,d2,d3, alA[kt*4],alA[kt*4+1],alA[kt*4+2],alA[kt*4+3], bh.x,bh.y);
            mma16816(d0,d1,d2,d3, ahA[kt*4],ahA[kt*4+1],ahA[kt*4+2],ahA[kt*4+3], bl.x,bl.y);
            mma16816(d4,d5,d6,d7, ahB[kt*4],ahB[kt*4+1],ahB[kt*4+2],ahB[kt*4+3], bh.x,bh.y);
            mma16816(d4,d5,d6,d7, alB[kt*4],alB[kt*4+1],alB[kt*4+2],alB[kt*4+3], bh.x,bh.y);
            mma16816(d4,d5,d6,d7, ahB[kt*4],ahB[kt*4+1],ahB[kt*4+2],ahB[kt*4+3], bl.x,bl.y);
        }
        D[nt*8+0]=d0; D[nt*8+1]=d1; D[nt*8+2]=d2; D[nt*8+3]=d3;
        D[nt*8+4]=d4; D[nt*8+5]=d5; D[nt*8+6]=d6; D[nt*8+7]=d7;
    }
}

// Build A fragments (hi/lo) for rows r0, r0+8 of a row-major [*,64] fp32 matrix.
__device__ __forceinline__ void load_a_frags(const float* M, int r0,
                                             int q2, u32* ah, u32* al)
{
    #pragma unroll
    for (int rr = 0; rr < 2; rr++) {
        const float* Mr = M + (size_t)(r0 + rr * 8) * 64;
        #pragma unroll
        for (int kt = 0; kt < 4; kt++) {
            const int c0 = kt * 16 + q2;
            const float2 pa = *reinterpret_cast<const float2*>(Mr + c0);
            const float2 pb = *reinterpret_cast<const float2*>(Mr + c0 + 8);
            split2(pa.x, pa.y, ah[kt*4 + rr],     al[kt*4 + rr]);
            split2(pb.x, pb.y, ah[kt*4 + 2 + rr], al[kt*4 + 2 + rr]);
        }
    }
}

// ---------------------------------------------------------------------------
// Kernel 1: HMMA per-vocab precompute of P and A1B.
// ---------------------------------------------------------------------------
__global__ void __launch_bounds__(256) k_pre(const float* __restrict__ u2e)
{
    __shared__ u32 sBF[8192];        // L=3 (W1) and L=4 frag blocks, 32KB

    const int tid = threadIdx.x;
    {
        const uint4* src = reinterpret_cast<const uint4*>(g_Wf + 3 * 4096);
        uint4* dst = reinterpret_cast<uint4*>(sBF);
        for (int i = tid; i < 2048; i += 256) dst[i] = src[i];
    }
    __syncthreads();

    const int wid  = tid >> 5;
    const int lane = tid & 31;
    const int g    = lane >> 2;
    const int q2   = (lane & 3) << 1;

    const int wt = blockIdx.x * 8 + wid;
    if (wt >= VTILE) return;
    const int v0 = wt * 16 + g;
    const int v1 = v0 + 8;

    u32 ah[16], al[16];
    load_a_frags(u2e, wt * 16 + g, q2, ah, al);

    float D[32];

    gemm64(D, ah, al, sBF, lane);
    #pragma unroll
    for (int nt = 0; nt < 8; nt++) {
        const int c0 = nt * 8 + q2;
        *reinterpret_cast<float2*>(g_P + (size_t)v0 * 64 + c0) = make_float2(D[nt*4+0], D[nt*4+1]);
        *reinterpret_cast<float2*>(g_P + (size_t)v1 * 64 + c0) = make_float2(D[nt*4+2], D[nt*4+3]);
    }

    gemm64(D, ah, al, sBF + 4096, lane);
    #pragma unroll
    for (int nt = 0; nt < 8; nt++) {
        const int c0 = nt * 8 + q2;
        *reinterpret_cast<float2*>(g_A1B + (size_t)v0 * 64 + c0) = make_float2(D[nt*4+0], D[nt*4+1]);
        *reinterpret_cast<float2*>(g_A1B + (size_t)v1 * 64 + c0) = make_float2(D[nt*4+2], D[nt*4+3]);
    }
}

// ---------------------------------------------------------------------------
// Main kernel: layers 1..4 + scores. Each warp processes 32 pairs (two m16
// tiles sharing B-fragment loads). Block = 4 warps = 128 pairs.
// ---------------------------------------------------------------------------
#define DSM_U32  (12288 + 512 + 5*64)   // 13120 u32 = 52480 B
#define DSM_BYTES (DSM_U32 * 4)

__global__ void __launch_bounds__(128, 2) k_main(
    const int*   __restrict__ nodes,
    const int*   __restrict__ nidx,
    const float* __restrict__ labels,
    const float* __restrict__ w1W,
    const float* __restrict__ w1b,
    const float* __restrict__ w2b,
    const float* __restrict__ a1b,
    const float* __restrict__ a2b,
    const float* __restrict__ a3W,
    const float* __restrict__ a3b)
{
    extern __shared__ u32 dsm[];
    u32*   sBF  = dsm;                       // 12288 u32 (48KB): L=0,1,2
    float* sW1L = (float*)(dsm + 12288);     // 512
    float* sB1  = sW1L + 512;
    float* sB2  = sB1 + 64;
    float* sBa1 = sB2 + 64;
    float* sBa2 = sBa1 + 64;
    float* sA3  = sBa2 + 64;

    const int tid = threadIdx.x;
    {
        const uint4* src = reinterpret_cast<const uint4*>(g_Wf);
        uint4* dst = reinterpret_cast<uint4*>(sBF);
        for (int i = tid; i < 3072; i += 128) dst[i] = src[i];
        for (int i = tid; i < 512; i += 128) sW1L[i] = w1W[4096 + i];
        if (tid < 64) {
            sB1 [tid] = w1b[tid];
            sB2 [tid] = w2b[tid];
            sBa1[tid] = a1b[tid];
            sBa2[tid] = a2b[tid];
            sA3 [tid] = a3W[tid];
        }
    }
    __syncthreads();

    const float a3b0 = a3b[0];
    const int wid  = tid >> 5;             // 0..3
    const int lane = tid & 31;
    const int g    = lane >> 2;            // 0..7  (row within m16 tile)
    const int q2   = (lane & 3) << 1;      // 0,2,4,6 (col pair base)

    for (int t = blockIdx.x; t < NTILE; t += gridDim.x) {
        const int pb = t * 128 + wid * 32 + g;   // rows pb, pb+8, pb+16, pb+24

        u32 ahA[16], alA[16], ahB[16], alB[16];

        // ================= LAYER 1 (scalar) → A fragments =================
        #pragma unroll
        for (int rr = 0; rr < 4; rr++) {
            const int p  = pb + rr * 8;
            u32* ah = (rr < 2) ? ahA : ahB;
            u32* al = (rr < 2) ? alA : alB;
            const int sl = rr & 1;

            const int ni = __ldg(&nidx[p]);
            const float* Pr = g_P + (size_t)ni * 64;
            const float4* lv = reinterpret_cast<const float4*>(labels + (size_t)p * 8);
            const float4 la = lv[0], lb = lv[1];
            const float lab[8] = { la.x, la.y, la.z, la.w, lb.x, lb.y, lb.z, lb.w };

            #pragma unroll
            for (int kt = 0; kt < 4; kt++) {
                const int c0 = kt * 16 + q2;
                const float2 pa = *reinterpret_cast<const float2*>(Pr + c0);
                const float2 pbv = *reinterpret_cast<const float2*>(Pr + c0 + 8);
                float v0 = pa.x + sB1[c0];
                float v1 = pa.y + sB1[c0 + 1];
                float v2 = pbv.x + sB1[c0 + 8];
                float v3 = pbv.y + sB1[c0 + 9];
                #pragma unroll
                for (int j = 0; j < 8; j++) {
                    const float* wr = sW1L + j * 64 + c0;
                    v0 = fmaf(lab[j], wr[0], v0);
                    v1 = fmaf(lab[j], wr[1], v1);
                    v2 = fmaf(lab[j], wr[8], v2);
                    v3 = fmaf(lab[j], wr[9], v3);
                }
                v0 = fmaxf(v0, 0.f); v1 = fmaxf(v1, 0.f);
                v2 = fmaxf(v2, 0.f); v3 = fmaxf(v3, 0.f);
                split2(v0, v1, ah[kt*4 + sl],     al[kt*4 + sl]);
                split2(v2, v3, ah[kt*4 + 2 + sl], al[kt*4 + 2 + sl]);
            }
        }

        float D[64];

        // ================= LAYER 2: o = relu(h @ W2 + b2) =================
        gemm64x2(D, ahA, alA, ahB, alB, sBF, lane);
        #pragma unroll
        for (int nt = 0; nt < 8; nt++) {
            const int c0 = nt * 8 + q2;
            const int kt = nt >> 1, hf = nt & 1;
            #pragma unroll
            for (int half = 0; half < 2; half++) {
                const float b0 = sB2[c0], b1 = sB2[c0 + 1];
                const float v0 = fmaxf(D[nt*8 + half*4 + 0] + b0, 0.f);
                const float v1 = fmaxf(D[nt*8 + half*4 + 1] + b1, 0.f);
                const float v2 = fmaxf(D[nt*8 + half*4 + 2] + b0, 0.f);
                const float v3 = fmaxf(D[nt*8 + half*4 + 3] + b1, 0.f);
                const int r0 = pb + half * 16;
                *reinterpret_cast<float2*>(g_O + (size_t)r0 * 64 + c0)       = make_float2(v0, v1);
                *reinterpret_cast<float2*>(g_O + (size_t)(r0 + 8) * 64 + c0) = make_float2(v2, v3);
                u32* ah = half ? ahB : ahA;
                u32* al = half ? alB : alA;
                split2(v0, v1, ah[kt*4 + hf*2 + 0], al[kt*4 + hf*2 + 0]);
                split2(v2, v3, ah[kt*4 + hf*2 + 1], al[kt*4 + hf*2 + 1]);
            }
        }

        // ============ LAYER 3: a = relu(o @ A1a + A1B[node] + b) ==========
        const float* G[4];
        #pragma unroll
        for (int rr = 0; rr < 4; rr++)
            G[rr] = g_A1B + (size_t)__ldg(&nodes[(pb + rr * 8) / K_N]) * 64;

        gemm64x2(D, ahA, alA, ahB, alB, sBF + 4096, lane);
        #pragma unroll
        for (int nt = 0; nt < 8; nt++) {
            const int c0 = nt * 8 + q2;
            const int kt = nt >> 1, hf = nt & 1;
            #pragma unroll
            for (int half = 0; half < 2; half++) {
                const float2 g0 = *reinterpret_cast<const float2*>(G[half*2]     + c0);
                const float2 g1 = *reinterpret_cast<const float2*>(G[half*2 + 1] + c0);
                const float b0 = sBa1[c0], b1 = sBa1[c0 + 1];
                const float v0 = fmaxf(D[nt*8 + half*4 + 0] + b0 + g0.x, 0.f);
                const float v1 = fmaxf(D[nt*8 + half*4 + 1] + b1 + g0.y, 0.f);
                const float v2 = fmaxf(D[nt*8 + half*4 + 2] + b0 + g1.x, 0.f);
                const float v3 = fmaxf(D[nt*8 + half*4 + 3] + b1 + g1.y, 0.f);
                u32* ah = half ? ahB : ahA;
                u32* al = half ? alB : alA;
                split2(v0, v1, ah[kt*4 + hf*2 + 0], al[kt*4 + hf*2 + 0]);
                split2(v2, v3, ah[kt*4 + hf*2 + 1], al[kt*4 + hf*2 + 1]);
            }
        }

        // ========= LAYER 4: a2 = relu(a @ A2 + b); score = a2 . a3 ========
        gemm64x2(D, ahA, alA, ahB, alB, sBF + 8192, lane);
        float s[4] = {0.f, 0.f, 0.f, 0.f};
        #pragma unroll
        for (int nt = 0; nt < 8; nt++) {
            const int c0 = nt * 8 + q2;
            const float b0 = sBa2[c0], b1 = sBa2[c0 + 1];
            const float w0 = sA3[c0],  w1 = sA3[c0 + 1];
            #pragma unroll
            for (int half = 0; half < 2; half++) {
                const float v0 = fmaxf(D[nt*8 + half*4 + 0] + b0, 0.f);
                const float v1 = fmaxf(D[nt*8 + half*4 + 1] + b1, 0.f);
                const float v2 = fmaxf(D[nt*8 + half*4 + 2] + b0, 0.f);
                const float v3 = fmaxf(D[nt*8 + half*4 + 3] + b1, 0.f);
                s[half*2]     = fmaf(v0, w0, fmaf(v1, w1, s[half*2]));
                s[half*2 + 1] = fmaf(v2, w0, fmaf(v3, w1, s[half*2 + 1]));
            }
        }
        #pragma unroll
        for (int rr = 0; rr < 4; rr++) {
            float sv = s[rr];
            sv += __shfl_xor_sync(0xffffffffu, sv, 1);
            sv += __shfl_xor_sync(0xffffffffu, sv, 2);
            if ((lane & 3) == 0) g_S[pb + rr * 8] = sv + a3b0;
        }
    }
}

// ---------------------------------------------------------------------------
// Kernel 3: masked softmax over K neighbors + weighted aggregate
// ---------------------------------------------------------------------------
__global__ void __launch_bounds__(256) k_agg(const int*   __restrict__ nodes,
                                             const int*   __restrict__ nlen,
                                             const float* __restrict__ u2e,
                                             float*       __restrict__ out)
{
    const int wid  = (blockIdx.x * 256 + threadIdx.x) >> 5;
    const int lane = threadIdx.x & 31;
    if (wid >= B_N) return;
    const int b   = wid;
    const int len = nlen[b];

    if (len <= 0) {
        const int node = nodes[b];
        const float2* src = reinterpret_cast<const float2*>(u2e + (size_t)node * 64);
        reinterpret_cast<float2*>(out + (size_t)b * 64)[lane] = src[lane];
        return;
    }

    const float* Sb = g_S + (size_t)b * K_N;
    float s0 = (lane      < len) ? Sb[lane]      : -3.0e38f;
    float s1 = (lane + 32 < len) ? Sb[lane + 32] : -3.0e38f;

    float m = fmaxf(s0, s1);
    #pragma unroll
    for (int o = 16; o > 0; o >>= 1) m = fmaxf(m, __shfl_xor_sync(0xffffffffu, m, o));

    const float e0 = (lane      < len) ? expf(s0 - m) : 0.f;
    const float e1 = (lane + 32 < len) ? expf(s1 - m) : 0.f;

    float ss = e0 + e1;
    #pragma unroll
    for (int o = 16; o > 0; o >>= 1) ss += __shfl_xor_sync(0xffffffffu, ss, o);

    const float inv = 1.f / ss;
    const float w0 = e0 * inv;
    const float w1 = e1 * inv;

    float2 agg = make_float2(0.f, 0.f);
    const float2* Ob = reinterpret_cast<const float2*>(g_O + (size_t)b * K_N * 64);
    for (int k = 0; k < len; k++) {
        const float ak = (k < 32) ? __shfl_sync(0xffffffffu, w0, k)
                                  : __shfl_sync(0xffffffffu, w1, k - 32);
        const float2 ov = Ob[k * 32 + lane];
        agg.x = fmaf(ak, ov.x, agg.x);
        agg.y = fmaf(ak, ov.y, agg.y);
    }
    reinterpret_cast<float2*>(out + (size_t)b * 64)[lane] = agg;
}

// ---------------------------------------------------------------------------
// kernel_launch
// ---------------------------------------------------------------------------
extern "C" void kernel_launch(void* const* d_in, const int* in_sizes, int n_in,
                              void* d_out, int out_size)
{
    const int*   nodes  = (const int*)  d_in[0];
    const int*   nidx   = (const int*)  d_in[1];
    const int*   nlen   = (const int*)  d_in[2];
    const float* labels = (const float*)d_in[3];
    const float* u2e    = (const float*)d_in[4];
    const float* w1W    = (const float*)d_in[5];
    const float* w1b    = (const float*)d_in[6];
    const float* w2W    = (const float*)d_in[7];
    const float* w2b    = (const float*)d_in[8];
    const float* a1W    = (const float*)d_in[9];
    const float* a1b    = (const float*)d_in[10];
    const float* a2W    = (const float*)d_in[11];
    const float* a2b    = (const float*)d_in[12];
    const float* a3W    = (const float*)d_in[13];
    const float* a3b    = (const float*)d_in[14];
    float* out = (float*)d_out;

    cudaFuncSetAttribute(k_main, cudaFuncAttributeMaxDynamicSharedMemorySize, DSM_BYTES);

    k_wfrag<<<20, 256>>>(w2W, a1W, a2W, w1W);
    k_pre  <<<(VTILE + 7) / 8, 256>>>(u2e);
    k_main <<<296, 128, DSM_BYTES>>>(nodes, nidx, labels, w1W, w1b,
                                     w2b, a1b, a2b, a3W, a3b);
    k_agg  <<<(B_N * 32 + 255) / 256, 256>>>(nodes, nlen, u2e, out);
}